// round 4
// baseline (speedup 1.0000x reference)
#include <cuda_runtime.h>
#include <cuda_bf16.h>

// Problem: CaptionDetectionTargetLayer (Mask-RCNN target sampling), B=8, N=4096, G=512, C=15
// Outputs (concatenated float32): rois[B,200,4], deltas[B,200,4], caps[B,200,15], scores[B,200]

#define T_ROIS   200
#define POS_MAX  66
#define MAXG     512
#define K1_BLOCK 256
#define K2_BLOCK 1024

__device__ unsigned char g_flags[8 * 4096];   // 0=invalid, 1=neg, 2=pos
__device__ short         g_argm [8 * 4096];   // argmax gt index per proposal

// ---------------------------------------------------------------------------
// Kernel 1: per-proposal masked IoU row-max + first-occurrence argmax
// ---------------------------------------------------------------------------
__global__ void iou_max_kernel(const float4* __restrict__ proposals,
                               const float4* __restrict__ gt,
                               int N, int G)
{
    int b = blockIdx.y;
    int i = blockIdx.x * blockDim.x + threadIdx.x;

    __shared__ float4        sg[MAXG];
    __shared__ float         sa2[MAXG];
    __shared__ unsigned char sv[MAXG];

    for (int j = threadIdx.x; j < G; j += blockDim.x) {
        float4 g = gt[(size_t)b * G + j];
        sg[j]  = g;
        sa2[j] = (g.z - g.x) * (g.w - g.y);
        sv[j]  = (fabsf(g.x) + fabsf(g.y) + fabsf(g.z) + fabsf(g.w)) > 0.0f;
    }
    __syncthreads();

    if (i >= N) return;

    float4 p  = proposals[(size_t)b * N + i];
    float  a1 = (p.z - p.x) * (p.w - p.y);
    bool   vp = (fabsf(p.x) + fabsf(p.y) + fabsf(p.z) + fabsf(p.w)) > 0.0f;

    float best = -2.0f;
    int   bi   = 0;
    #pragma unroll 4
    for (int j = 0; j < G; ++j) {
        float4 g = sg[j];
        float y1 = fmaxf(p.x, g.x);
        float x1 = fmaxf(p.y, g.y);
        float y2 = fminf(p.z, g.z);
        float x2 = fminf(p.w, g.w);
        float inter = fmaxf(x2 - x1, 0.0f) * fmaxf(y2 - y1, 0.0f);
        float uni   = a1 + sa2[j] - inter;
        float iou   = __fdiv_rn(inter, uni > 0.0f ? uni : 1.0f);
        float m     = sv[j] ? iou : -1.0f;
        if (m > best) { best = m; bi = j; }   // strict > : first-occurrence argmax
    }

    g_flags[b * N + i] = vp ? (best >= 0.5f ? 2 : 1) : 0;
    g_argm [b * N + i] = (short)bi;
}

// ---------------------------------------------------------------------------
// Kernel 2: per-image ordered compaction (prefix scan) + output scatter
// One block of 1024 threads per image; each thread owns 4 consecutive rois.
// ---------------------------------------------------------------------------
__global__ void select_kernel(const float4* __restrict__ proposals,
                              const float4* __restrict__ gt,
                              const int*    __restrict__ caps,
                              const float*  __restrict__ scores,
                              int N, int G, int C, int B,
                              float* __restrict__ out)
{
    const int b = blockIdx.x;
    const int t = threadIdx.x;
    const int per = (N + K2_BLOCK - 1) / K2_BLOCK;   // 4 for N=4096

    // local flag cache + counts
    unsigned char f[8];
    int pc = 0, nc = 0;
    int base = t * per;
    for (int k = 0; k < per; ++k) {
        int i = base + k;
        unsigned char fl = (i < N) ? g_flags[b * N + i] : (unsigned char)0;
        f[k] = fl;
        pc += (fl == 2);
        nc += (fl == 1);
    }

    // packed inclusive Hillis-Steele scan over 1024 threads
    __shared__ int s[K2_BLOCK];
    s[t] = (pc << 16) | nc;
    __syncthreads();
    for (int off = 1; off < K2_BLOCK; off <<= 1) {
        int v = (t >= off) ? s[t - off] : 0;
        __syncthreads();
        s[t] += v;
        __syncthreads();
    }
    int incl  = s[t];
    int total = s[K2_BLOCK - 1];
    int p_base = (incl >> 16) - pc;
    int n_base = (incl & 0xFFFF) - nc;
    int pos_total = total >> 16;
    int neg_total = total & 0xFFFF;

    int pos_cnt = min(pos_total, POS_MAX);
    // Replicate XLA's divide-by-constant -> multiply-by-reciprocal rewrite:
    //   neg_target = int32( f32(pos_cnt) * round_f32(1/0.33f) ) - pos_cnt
    // For pos_cnt=66: 66 * 3.0303029313 = 199.99999347 -> rounds to 200.0f -> 200.
    float rcp = __fdiv_rn(1.0f, 0.33f);
    int neg_target = (int)__fmul_rn((float)pos_cnt, rcp) - pos_cnt;
    int neg_cnt = min(min(neg_target, neg_total), T_ROIS - pos_cnt);
    if (neg_cnt < 0) neg_cnt = 0;

    // output section pointers (float32 concat: rois | deltas | caps | scores)
    float* rois    = out + (size_t)b * T_ROIS * 4;
    float* deltas  = out + (size_t)B * T_ROIS * 4 + (size_t)b * T_ROIS * 4;
    float* ocaps   = out + (size_t)2 * B * T_ROIS * 4 + (size_t)b * T_ROIS * C;
    float* oscores = out + (size_t)B * T_ROIS * (8 + C) + (size_t)b * T_ROIS;

    // zero-fill this image's output slices (buffer is poisoned by harness)
    for (int k = t; k < T_ROIS * 4; k += K2_BLOCK) { rois[k] = 0.0f; deltas[k] = 0.0f; }
    for (int k = t; k < T_ROIS * C; k += K2_BLOCK) ocaps[k] = 0.0f;
    for (int k = t; k < T_ROIS;     k += K2_BLOCK) oscores[k] = 0.0f;
    __syncthreads();

    int pr = p_base, nr = n_base;
    for (int k = 0; k < per; ++k) {
        int i = base + k;
        if (f[k] == 2) {
            if (pr < pos_cnt) {
                float4 p = proposals[(size_t)b * N + i];
                rois[pr * 4 + 0] = p.x;
                rois[pr * 4 + 1] = p.y;
                rois[pr * 4 + 2] = p.z;
                rois[pr * 4 + 3] = p.w;

                int gi = g_argm[b * N + i];
                float4 g = gt[(size_t)b * G + gi];
                float h  = p.z - p.x, w  = p.w - p.y;
                float cy = p.x + 0.5f * h, cx = p.y + 0.5f * w;
                float gh = g.z - g.x, gw = g.w - g.y;
                float gcy = g.x + 0.5f * gh, gcx = g.y + 0.5f * gw;
                deltas[pr * 4 + 0] = __fdiv_rn(__fdiv_rn(gcy - cy, h), 0.1f);
                deltas[pr * 4 + 1] = __fdiv_rn(__fdiv_rn(gcx - cx, w), 0.1f);
                deltas[pr * 4 + 2] = __fdiv_rn(logf(__fdiv_rn(gh, h)), 0.2f);
                deltas[pr * 4 + 3] = __fdiv_rn(logf(__fdiv_rn(gw, w)), 0.2f);

                const int* cp = caps + ((size_t)b * G + gi) * C;
                for (int c = 0; c < C; ++c)
                    ocaps[pr * C + c] = (float)cp[c];
                oscores[pr] = scores[(size_t)b * G + gi];
            }
            pr++;
        } else if (f[k] == 1) {
            if (nr < neg_cnt) {
                float4 p = proposals[(size_t)b * N + i];
                int slot = pos_cnt + nr;
                rois[slot * 4 + 0] = p.x;
                rois[slot * 4 + 1] = p.y;
                rois[slot * 4 + 2] = p.z;
                rois[slot * 4 + 3] = p.w;
            }
            nr++;
        }
    }
}

// ---------------------------------------------------------------------------
extern "C" void kernel_launch(void* const* d_in, const int* in_sizes, int n_in,
                              void* d_out, int out_size)
{
    const float4* proposals = (const float4*)d_in[0];
    const float4* gt_boxes  = (const float4*)d_in[1];
    const int*    captions  = (const int*)  d_in[2];
    const float*  scores    = (const float*)d_in[3];
    float*        out       = (float*)d_out;

    const int N = 4096;
    int B = in_sizes[0] / (4 * N);         // 8
    int G = in_sizes[3] / B;               // 512
    int C = in_sizes[2] / in_sizes[3];     // 15

    dim3 grid1((N + K1_BLOCK - 1) / K1_BLOCK, B);
    iou_max_kernel<<<grid1, K1_BLOCK>>>(proposals, gt_boxes, N, G);

    select_kernel<<<B, K2_BLOCK>>>(proposals, gt_boxes, captions, scores,
                                   N, G, C, B, out);
}

// round 7
// speedup vs baseline: 2.3380x; 2.3380x over previous
#include <cuda_runtime.h>
#include <cuda_bf16.h>
#include <math_constants.h>

// CaptionDetectionTargetLayer: B=8, N=4096, G=512, C=15
// Outputs (concat float32): rois[B,200,4] | deltas[B,200,4] | caps[B,200,15] | scores[B,200]

#define T_ROIS   200
#define POS_MAX  66
#define MAXG     512
#define K1_BLOCK 256
#define K2_BLOCK 1024

__device__ unsigned char g_flags[8 * 4096];   // 0=invalid, 1=neg, 2=pos
__device__ short         g_argm [8 * 4096];   // argmax gt index per proposal

// ---------------------------------------------------------------------------
// Kernel 1: per-proposal masked IoU row-max + first-occurrence argmax.
// Division-free mainloop: ratio comparison by cross-multiplication with an
// fp32 guard band; exact f64-product tiebreak in the (rare) ambiguous band.
// One __fdiv_rn at the end reproduces the reference's rounded max value.
// ---------------------------------------------------------------------------
__global__ void iou_max_kernel(const float4* __restrict__ proposals,
                               const float4* __restrict__ gt,
                               int N, int G)
{
    int b = blockIdx.y;
    int i = blockIdx.x * blockDim.x + threadIdx.x;

    __shared__ float4 sg[MAXG];
    __shared__ float  sa2[MAXG];   // gt area; +inf marks invalid gt (never wins)

    for (int j = threadIdx.x; j < G; j += blockDim.x) {
        float4 g = gt[(size_t)b * G + j];
        sg[j] = g;
        float a2 = (g.z - g.x) * (g.w - g.y);
        bool vg  = (fabsf(g.x) + fabsf(g.y) + fabsf(g.z) + fabsf(g.w)) > 0.0f;
        sa2[j] = vg ? a2 : CUDART_INF_F;
    }
    __syncthreads();

    if (i >= N) return;

    float4 p  = proposals[(size_t)b * N + i];
    float  a1 = (p.z - p.x) * (p.w - p.y);
    bool   vp = (fabsf(p.x) + fabsf(p.y) + fabsf(p.z) + fabsf(p.w)) > 0.0f;

    // best ratio = best_inter / best_d, initialized to 0/1 (== IoU 0, idx 0)
    float best_inter = 0.0f;
    float best_d     = 1.0f;
    int   bi         = 0;

    #pragma unroll 4
    for (int j = 0; j < G; ++j) {
        float4 g  = sg[j];
        float  a2 = sa2[j];
        float y1 = fmaxf(p.x, g.x);
        float x1 = fmaxf(p.y, g.y);
        float y2 = fminf(p.z, g.z);
        float x2 = fminf(p.w, g.w);
        float inter = fmaxf(x2 - x1, 0.0f) * fmaxf(y2 - y1, 0.0f);
        float uni   = a1 + a2 - inter;              // +inf for invalid gt
        float d     = uni > 0.0f ? uni : 1.0f;

        // compare inter/d  vs  best_inter/best_d  (both nonnegative)
        float lhs = __fmul_rn(inter, best_d);
        float rhs = __fmul_rn(best_inter, d);       // inf or NaN for invalid gt
        if (lhs > __fmul_rn(rhs, 1.000001f)) {      // definitely greater
            best_inter = inter; best_d = d; bi = j;
        } else if (lhs > __fmul_rn(rhs, 0.999999f)) {
            // ambiguous band: exact compare (f32*f32 is exact in f64)
            double dl = (double)inter * (double)best_d;
            double dr = (double)best_inter * (double)d;
            if (dl > dr) { best_inter = inter; best_d = d; bi = j; }
        }
    }

    float best_iou = __fdiv_rn(best_inter, best_d); // reference's rounded value
    g_flags[b * N + i] = vp ? (best_iou >= 0.5f ? 2 : 1) : 0;
    g_argm [b * N + i] = (short)bi;
}

// ---------------------------------------------------------------------------
// Kernel 2: per-image ordered compaction (warp-shfl scan) + output scatter.
// One block of 1024 threads per image; each thread owns 4 consecutive rois.
// ---------------------------------------------------------------------------
__global__ void select_kernel(const float4* __restrict__ proposals,
                              const float4* __restrict__ gt,
                              const int*    __restrict__ caps,
                              const float*  __restrict__ scores,
                              int N, int G, int C, int B,
                              float* __restrict__ out)
{
    const int b    = blockIdx.x;
    const int t    = threadIdx.x;
    const int lane = t & 31;
    const int wid  = t >> 5;
    const int per  = N / K2_BLOCK;                  // 4

    // load 4 flags as one word; count pos/neg
    unsigned int fl4 = ((const unsigned int*)(g_flags + b * N))[t];
    unsigned char f[4];
    int pc = 0, nc = 0;
    #pragma unroll
    for (int k = 0; k < 4; ++k) {
        f[k] = (fl4 >> (8 * k)) & 0xFF;
        pc += (f[k] == 2);
        nc += (f[k] == 1);
    }

    // packed (pos<<16 | neg) inclusive warp scan
    int v = (pc << 16) | nc;
    int incl = v;
    #pragma unroll
    for (int off = 1; off < 32; off <<= 1) {
        int n = __shfl_up_sync(0xFFFFFFFFu, incl, off);
        if (lane >= off) incl += n;
    }

    __shared__ int swarp[33];                       // [32] = grand total
    if (lane == 31) swarp[wid] = incl;
    __syncthreads();
    if (wid == 0) {
        int wv = swarp[lane];
        int wincl = wv;
        #pragma unroll
        for (int off = 1; off < 32; off <<= 1) {
            int n = __shfl_up_sync(0xFFFFFFFFu, wincl, off);
            if (lane >= off) wincl += n;
        }
        swarp[lane] = wincl - wv;                   // exclusive warp prefix
        if (lane == 31) swarp[32] = wincl;          // grand total
    }
    __syncthreads();

    int excl   = swarp[wid] + incl - v;             // exclusive over all threads
    int total  = swarp[32];
    int p_base = excl >> 16;
    int n_base = excl & 0xFFFF;
    int pos_total = total >> 16;
    int neg_total = total & 0xFFFF;

    int pos_cnt = min(pos_total, POS_MAX);
    // Replicate XLA's div-by-const -> mul-by-reciprocal rewrite:
    // 66 * round_f32(1/0.33) = 199.99999347 -> rounds to 200.0f -> 200.
    float rcp = __fdiv_rn(1.0f, 0.33f);
    int neg_target = (int)__fmul_rn((float)pos_cnt, rcp) - pos_cnt;
    int neg_cnt = min(min(neg_target, neg_total), T_ROIS - pos_cnt);
    if (neg_cnt < 0) neg_cnt = 0;

    // output sections
    float* rois    = out + (size_t)b * T_ROIS * 4;
    float* deltas  = out + (size_t)B * T_ROIS * 4 + (size_t)b * T_ROIS * 4;
    float* ocaps   = out + (size_t)2 * B * T_ROIS * 4 + (size_t)b * T_ROIS * C;
    float* oscores = out + (size_t)B * T_ROIS * (8 + C) + (size_t)b * T_ROIS;

    // zero-fill this image's slices (harness poisons the buffer)
    for (int k = t; k < T_ROIS * 4; k += K2_BLOCK) { rois[k] = 0.0f; deltas[k] = 0.0f; }
    for (int k = t; k < T_ROIS * C; k += K2_BLOCK) ocaps[k] = 0.0f;
    for (int k = t; k < T_ROIS;     k += K2_BLOCK) oscores[k] = 0.0f;
    __syncthreads();

    int pr = p_base, nr = n_base;
    int base = t * per;
    #pragma unroll
    for (int k = 0; k < 4; ++k) {
        int i = base + k;
        if (f[k] == 2) {
            if (pr < pos_cnt) {
                float4 p = proposals[(size_t)b * N + i];
                rois[pr * 4 + 0] = p.x;
                rois[pr * 4 + 1] = p.y;
                rois[pr * 4 + 2] = p.z;
                rois[pr * 4 + 3] = p.w;

                int gi = g_argm[b * N + i];
                float4 g = gt[(size_t)b * G + gi];
                float h  = p.z - p.x, w  = p.w - p.y;
                float cy = p.x + 0.5f * h, cx = p.y + 0.5f * w;
                float gh = g.z - g.x, gw = g.w - g.y;
                float gcy = g.x + 0.5f * gh, gcx = g.y + 0.5f * gw;
                deltas[pr * 4 + 0] = __fdiv_rn(__fdiv_rn(gcy - cy, h), 0.1f);
                deltas[pr * 4 + 1] = __fdiv_rn(__fdiv_rn(gcx - cx, w), 0.1f);
                deltas[pr * 4 + 2] = __fdiv_rn(logf(__fdiv_rn(gh, h)), 0.2f);
                deltas[pr * 4 + 3] = __fdiv_rn(logf(__fdiv_rn(gw, w)), 0.2f);

                const int* cp = caps + ((size_t)b * G + gi) * C;
                #pragma unroll
                for (int c = 0; c < 15; ++c)
                    ocaps[pr * C + c] = (float)cp[c];
                oscores[pr] = scores[(size_t)b * G + gi];
            }
            pr++;
        } else if (f[k] == 1) {
            if (nr < neg_cnt) {
                float4 p = proposals[(size_t)b * N + i];
                int slot = pos_cnt + nr;
                rois[slot * 4 + 0] = p.x;
                rois[slot * 4 + 1] = p.y;
                rois[slot * 4 + 2] = p.z;
                rois[slot * 4 + 3] = p.w;
            }
            nr++;
        }
    }
}

// ---------------------------------------------------------------------------
extern "C" void kernel_launch(void* const* d_in, const int* in_sizes, int n_in,
                              void* d_out, int out_size)
{
    const float4* proposals = (const float4*)d_in[0];
    const float4* gt_boxes  = (const float4*)d_in[1];
    const int*    captions  = (const int*)  d_in[2];
    const float*  scores    = (const float*)d_in[3];
    float*        out       = (float*)d_out;

    const int N = 4096;
    int B = in_sizes[0] / (4 * N);         // 8
    int G = in_sizes[3] / B;               // 512
    int C = in_sizes[2] / in_sizes[3];     // 15

    dim3 grid1((N + K1_BLOCK - 1) / K1_BLOCK, B);
    iou_max_kernel<<<grid1, K1_BLOCK>>>(proposals, gt_boxes, N, G);

    select_kernel<<<B, K2_BLOCK>>>(proposals, gt_boxes, captions, scores,
                                   N, G, C, B, out);
}